// round 14
// baseline (speedup 1.0000x reference)
#include <cuda_runtime.h>
#include <cuda_fp16.h>
#include <cstdint>

#define HEADS 6
#define HD 32
#define CDIM 192
#define NQ 576
#define DISP 4
#define IMG 256
#define BATCH 4
#define TOK 64
#define NWIN 1024
#define MTOT (BATCH * IMG * IMG)
#define ATT_SCALE 0.17677669529663687f

// scratch (allocation-free rule: __device__ globals) — fp16 intermediates
__device__ __half g_qkv[(size_t)MTOT * NQ];     // ROLLED coords, [m, 576]
__device__ __half g_attn[(size_t)MTOT * CDIM];  // ROLLED coords, [m, 192]
__device__ float g_bias[TOK * TOK];
__device__ __half g_wqkv_h[NQ * CDIM];          // fp16 weights (pre-converted)
__device__ __half g_wout_h[CDIM * CDIM];

// ---------------------------------------------------------------------------
// mma.sync / ldmatrix helpers (fp16, fp32 accumulate)
// ---------------------------------------------------------------------------
__device__ __forceinline__ void mma_f16(float* c, const uint32_t* a, const uint32_t* b) {
    asm volatile(
        "mma.sync.aligned.m16n8k16.row.col.f32.f16.f16.f32 "
        "{%0,%1,%2,%3}, {%4,%5,%6,%7}, {%8,%9}, {%0,%1,%2,%3};"
        : "+f"(c[0]), "+f"(c[1]), "+f"(c[2]), "+f"(c[3])
        : "r"(a[0]), "r"(a[1]), "r"(a[2]), "r"(a[3]), "r"(b[0]), "r"(b[1]));
}
__device__ __forceinline__ uint32_t smem_u32(const void* p) {
    uint32_t a;
    asm("{ .reg .u64 t; cvta.to.shared.u64 t, %1; cvt.u32.u64 %0, t; }" : "=r"(a) : "l"(p));
    return a;
}
__device__ __forceinline__ void ldsm_x4(uint32_t* r, uint32_t addr) {
    asm volatile("ldmatrix.sync.aligned.m8n8.x4.shared.b16 {%0,%1,%2,%3}, [%4];"
                 : "=r"(r[0]), "=r"(r[1]), "=r"(r[2]), "=r"(r[3]) : "r"(addr));
}
__device__ __forceinline__ void ldsm_x4_t(uint32_t* r, uint32_t addr) {
    asm volatile("ldmatrix.sync.aligned.m8n8.x4.trans.shared.b16 {%0,%1,%2,%3}, [%4];"
                 : "=r"(r[0]), "=r"(r[1]), "=r"(r[2]), "=r"(r[3]) : "r"(addr));
}
__device__ __forceinline__ uint32_t packh2(float a, float b) {
    __half2 h = __floats2half2_rn(a, b);
    return *reinterpret_cast<uint32_t*>(&h);
}

// GEMM smem: BM=128 rows A + 64 rows B, 200 halves/row (400B ≡ 16 mod 128 -> ldsm conflict-free)
#define AST2 200
#define AG_H (128 * AST2)
#define BG_H (64 * AST2)
#define SMEM_G ((AG_H + BG_H) * 2)   // 76800 B -> 2 CTAs/SM

// ---------------------------------------------------------------------------
// Kernel 0a: gather rel-pos bias table;  0b: weights fp32 -> fp16
// ---------------------------------------------------------------------------
__global__ void bias_kernel(const float* __restrict__ pos) {
    int idx = blockIdx.x * blockDim.x + threadIdx.x;
    if (idx < TOK * TOK) {
        int i = idx >> 6, j = idx & 63;
        g_bias[idx] = pos[((i >> 3) - (j >> 3) + 7) * 15 + ((i & 7) - (j & 7) + 7)];
    }
}
__global__ void wconv_kernel(const float* __restrict__ wqkv, const float* __restrict__ wout) {
    int idx = blockIdx.x * blockDim.x + threadIdx.x;
    if (idx < NQ * CDIM)   g_wqkv_h[idx] = __float2half_rn(wqkv[idx]);
    if (idx < CDIM * CDIM) g_wout_h[idx] = __float2half_rn(wout[idx]);
}

// ---------------------------------------------------------------------------
// Kernel 1: QKV GEMM (fp16 m16n8k16). BM=128, 256 thr, 8 warps (4m x 2n),
// warp tile 32x32. B tiles: raw fp16 copies. Roll folded into A-load.
// ---------------------------------------------------------------------------
__global__ __launch_bounds__(256, 2) void qkv_tc(const float* __restrict__ x) {
    extern __shared__ __half smh[];
    __half* As = smh;
    __half* Bsh = smh + AG_H;
    uint32_t sbase = smem_u32(smh);
    uint32_t bbase = sbase + AG_H * 2;

    int tid = threadIdx.x;
    int wid = tid >> 5, lane = tid & 31;
    int warp_m = (wid >> 1) * 32;      // 4 m-warps
    int warp_n = (wid & 1) * 32;       // 2 n-warps
    int lr = lane >> 2, lc = lane & 3;
    int m0 = blockIdx.x * 128;

    uint32_t aoff0 = sbase + (uint32_t)((warp_m + (lane & 7) + ((lane >> 3) & 1) * 8) * (AST2 * 2)
                                        + ((lane >> 4) & 1) * 16);
    uint32_t aoff1 = aoff0 + 16 * (AST2 * 2);
    uint32_t boff0 = bbase + (uint32_t)((warp_n + (lane & 7) + ((lane >> 4) & 1) * 8) * (AST2 * 2)
                                        + ((lane >> 3) & 1) * 16);
    uint32_t boff1 = boff0 + 16 * (AST2 * 2);

    // A tile 128x192 fp32 -> fp16, roll folded in. 6144 float4 / 256 thr.
    #pragma unroll
    for (int j = 0; j < 24; j++) {
        int i = tid + j * 256;
        int r = i / 48, c4 = i % 48;
        int m = m0 + r;
        int bb = m >> 16, y = (m >> 8) & 255, xx = m & 255;
        int ys = (y + DISP) & 255, xs = (xx + DISP) & 255;
        float4 v = *(const float4*)(x + ((size_t)((bb * IMG + ys) * IMG + xs)) * CDIM + c4 * 4);
        *(__half2*)&As[r * AST2 + c4 * 4]     = __floats2half2_rn(v.x, v.y);
        *(__half2*)&As[r * AST2 + c4 * 4 + 2] = __floats2half2_rn(v.z, v.w);
    }

    for (int t = 0; t < 9; t++) {
        int n0 = t * 64;
        __syncthreads();   // prev-tile readers done (covers A-load on t=0 too)
        #pragma unroll
        for (int j = 0; j < 6; j++) {        // 64 rows x 24 16B-chunks, raw fp16
            int i = tid + j * 256;
            int r = i / 24, c = i % 24;
            *(uint4*)&Bsh[r * AST2 + c * 8] =
                *(const uint4*)(g_wqkv_h + (size_t)(n0 + r) * CDIM + c * 8);
        }
        __syncthreads();

        float acc[2][4][4] = {};
        #pragma unroll
        for (int kk = 0; kk < 12; kk++) {        // K=192 in k16 steps
            uint32_t kb = (uint32_t)(kk * 32);   // 16 halves
            uint32_t a0[4], a1[4], b0[4], b1[4];
            ldsm_x4(a0, aoff0 + kb);
            ldsm_x4(a1, aoff1 + kb);
            ldsm_x4(b0, boff0 + kb);
            ldsm_x4(b1, boff1 + kb);
            mma_f16(acc[0][0], a0, b0);     mma_f16(acc[0][1], a0, b0 + 2);
            mma_f16(acc[0][2], a0, b1);     mma_f16(acc[0][3], a0, b1 + 2);
            mma_f16(acc[1][0], a1, b0);     mma_f16(acc[1][1], a1, b0 + 2);
            mma_f16(acc[1][2], a1, b1);     mma_f16(acc[1][3], a1, b1 + 2);
        }

        // Epilogue: fp16 stores, natural [m][576] layout.
        #pragma unroll
        for (int mt = 0; mt < 2; mt++) {
            size_t r0 = (size_t)(m0 + warp_m + mt * 16 + lr) * NQ + n0 + warp_n;
            size_t r1 = r0 + 8 * NQ;
            #pragma unroll
            for (int nt = 0; nt < 4; nt++) {
                int col = nt * 8 + lc * 2;
                *(__half2*)(g_qkv + r0 + col) = __floats2half2_rn(acc[mt][nt][0], acc[mt][nt][1]);
                *(__half2*)(g_qkv + r1 + col) = __floats2half2_rn(acc[mt][nt][2], acc[mt][nt][3]);
            }
        }
    }
}

// ---------------------------------------------------------------------------
// Kernel 2: windowed attention, fp16 MMA. Block = (b, win, head), 128 thr.
// P converted C-frag -> A-frag IN REGISTERS (no smem roundtrip);
// bias read directly from gmem (L1/L2-resident) — no smem staging.
// ---------------------------------------------------------------------------
#define QST2 40    // Q/K/V row stride (halves): 80B ≡ 16 mod 128 -> conflict-free

__global__ __launch_bounds__(128) void attn_mma() {
    __shared__ __half qkvs[3 * 64 * QST2];  // Q | K | V, each [64][40]

    int bid = blockIdx.x;
    int head = bid % HEADS;
    int t2 = bid / HEADS;
    int win = t2 & (NWIN - 1);
    int bb = t2 >> 10;
    int wy = win >> 5, wx = win & 31;

    int tid = threadIdx.x;
    int wid = tid >> 5, lane = tid & 31;
    int lr = lane >> 2, lc = lane & 3;
    int r_base = wid * 16;

    uint32_t qbase = smem_u32(qkvs);
    uint32_t kbase = qbase + 64 * QST2 * 2;
    uint32_t vbase = kbase + 64 * QST2 * 2;

    // ---- load Q,K,V (fp16 raw 16B chunks) ----
    #pragma unroll
    for (int l = 0; l < 6; l++) {
        int idx = tid + l * 128;            // 768 = 3 tensors x 64 tok x 4 chunks
        int tsel = idx >> 8;
        int rem = idx & 255;
        int j = rem >> 2, c = rem & 3;
        int y = wy * 8 + (j >> 3), xx = wx * 8 + (j & 7);
        size_t base = ((size_t)((bb * IMG + y) * IMG + xx)) * NQ + tsel * CDIM + head * HD + c * 8;
        *(uint4*)&qkvs[tsel * 64 * QST2 + j * QST2 + c * 8] = *(const uint4*)(g_qkv + base);
    }
    __syncthreads();

    // ---- S = Q K^T * scale + bias (bias straight from gmem) ----
    uint32_t qoff = qbase + (uint32_t)((r_base + (lane & 7) + ((lane >> 3) & 1) * 8) * (QST2 * 2)
                                       + ((lane >> 4) & 1) * 16);
    uint32_t qa[2][4];
    ldsm_x4(qa[0], qoff);
    ldsm_x4(qa[1], qoff + 32);

    float s[8][4] = {};
    #pragma unroll
    for (int p = 0; p < 4; p++) {          // nt pairs (16 kv tokens each)
        uint32_t koff = kbase + (uint32_t)((p * 16 + (lane & 7) + ((lane >> 4) & 1) * 8) * (QST2 * 2)
                                           + ((lane >> 3) & 1) * 16);
        #pragma unroll
        for (int kk = 0; kk < 2; kk++) {
            uint32_t kb[4];
            ldsm_x4(kb, koff + kk * 32);
            mma_f16(s[2 * p],     qa[kk], kb);
            mma_f16(s[2 * p + 1], qa[kk], kb + 2);
        }
    }

    int row0 = r_base + lr, row1 = r_base + lr + 8;
    #pragma unroll
    for (int nt = 0; nt < 8; nt++) {
        int col = nt * 8 + lc * 2;
        float2 b0 = *(const float2*)(g_bias + row0 * TOK + col);
        float2 b1 = *(const float2*)(g_bias + row1 * TOK + col);
        s[nt][0] = s[nt][0] * ATT_SCALE + b0.x;
        s[nt][1] = s[nt][1] * ATT_SCALE + b0.y;
        s[nt][2] = s[nt][2] * ATT_SCALE + b1.x;
        s[nt][3] = s[nt][3] * ATT_SCALE + b1.y;
    }

    // ---- softmax (rows row0/row1; reduce across quad lanes) ----
    float mx0 = -1e30f, mx1 = -1e30f;
    #pragma unroll
    for (int nt = 0; nt < 8; nt++) {
        mx0 = fmaxf(mx0, fmaxf(s[nt][0], s[nt][1]));
        mx1 = fmaxf(mx1, fmaxf(s[nt][2], s[nt][3]));
    }
    mx0 = fmaxf(mx0, __shfl_xor_sync(0xffffffff, mx0, 1));
    mx0 = fmaxf(mx0, __shfl_xor_sync(0xffffffff, mx0, 2));
    mx1 = fmaxf(mx1, __shfl_xor_sync(0xffffffff, mx1, 1));
    mx1 = fmaxf(mx1, __shfl_xor_sync(0xffffffff, mx1, 2));
    float sum0 = 0.f, sum1 = 0.f;
    #pragma unroll
    for (int nt = 0; nt < 8; nt++) {
        s[nt][0] = __expf(s[nt][0] - mx0); sum0 += s[nt][0];
        s[nt][1] = __expf(s[nt][1] - mx0); sum0 += s[nt][1];
        s[nt][2] = __expf(s[nt][2] - mx1); sum1 += s[nt][2];
        s[nt][3] = __expf(s[nt][3] - mx1); sum1 += s[nt][3];
    }
    sum0 += __shfl_xor_sync(0xffffffff, sum0, 1);
    sum0 += __shfl_xor_sync(0xffffffff, sum0, 2);
    sum1 += __shfl_xor_sync(0xffffffff, sum1, 1);
    sum1 += __shfl_xor_sync(0xffffffff, sum1, 2);
    float inv0 = 1.f / sum0, inv1 = 1.f / sum1;

    // ---- O = P V: P built in registers (C-frag == A-frag layout) ----
    float o[4][4] = {};
    #pragma unroll
    for (int kk = 0; kk < 4; kk++) {       // 16 kv tokens per step
        uint32_t pa[4];
        pa[0] = packh2(s[2 * kk][0],     s[2 * kk][1]);
        pa[1] = packh2(s[2 * kk][2],     s[2 * kk][3]);
        pa[2] = packh2(s[2 * kk + 1][0], s[2 * kk + 1][1]);
        pa[3] = packh2(s[2 * kk + 1][2], s[2 * kk + 1][3]);
        #pragma unroll
        for (int q = 0; q < 2; q++) {      // n blocks of 16 (d-cols)
            uint32_t voff = vbase + (uint32_t)((kk * 16 + (lane & 7) + ((lane >> 3) & 1) * 8) * (QST2 * 2)
                                               + (q * 16 + ((lane >> 4) & 1) * 8) * 2);
            uint32_t vb[4];
            ldsm_x4_t(vb, voff);
            mma_f16(o[2 * q],     pa, vb);
            mma_f16(o[2 * q + 1], pa, vb + 2);
        }
    }

    // ---- epilogue: scale by 1/sum, write g_attn fp16 (rolled coords) ----
    {
        int i0 = r_base + lr;
        int y0 = wy * 8 + (i0 >> 3), x0 = wx * 8 + (i0 & 7);
        int i1 = i0 + 8;
        int y1 = wy * 8 + (i1 >> 3), x1 = wx * 8 + (i1 & 7);
        __half* p0 = g_attn + ((size_t)((bb * IMG + y0) * IMG + x0)) * CDIM + head * HD;
        __half* p1 = g_attn + ((size_t)((bb * IMG + y1) * IMG + x1)) * CDIM + head * HD;
        #pragma unroll
        for (int nt = 0; nt < 4; nt++) {
            int col = nt * 8 + lc * 2;
            *(__half2*)(p0 + col) = __floats2half2_rn(o[nt][0] * inv0, o[nt][1] * inv0);
            *(__half2*)(p1 + col) = __floats2half2_rn(o[nt][2] * inv1, o[nt][3] * inv1);
        }
    }
}

// ---------------------------------------------------------------------------
// Kernel 3: output projection (fp16 MMA) + bias; roll-back on store.
// BM=128, 256 thr, same shape as qkv_tc. Output fp32.
// ---------------------------------------------------------------------------
__global__ __launch_bounds__(256, 2) void out_tc(const float* __restrict__ bout,
                                                 float* __restrict__ out) {
    extern __shared__ __half smh[];
    __half* As = smh;
    __half* Bsh = smh + AG_H;
    uint32_t sbase = smem_u32(smh);
    uint32_t bbase = sbase + AG_H * 2;

    int tid = threadIdx.x;
    int wid = tid >> 5, lane = tid & 31;
    int warp_m = (wid >> 1) * 32;
    int warp_n = (wid & 1) * 32;
    int lr = lane >> 2, lc = lane & 3;
    int m0 = blockIdx.x * 128;

    uint32_t aoff0 = sbase + (uint32_t)((warp_m + (lane & 7) + ((lane >> 3) & 1) * 8) * (AST2 * 2)
                                        + ((lane >> 4) & 1) * 16);
    uint32_t aoff1 = aoff0 + 16 * (AST2 * 2);
    uint32_t boff0 = bbase + (uint32_t)((warp_n + (lane & 7) + ((lane >> 4) & 1) * 8) * (AST2 * 2)
                                        + ((lane >> 3) & 1) * 16);
    uint32_t boff1 = boff0 + 16 * (AST2 * 2);

    // A tile: raw fp16 16B copies. 128 rows x 24 chunks / 256 thr.
    #pragma unroll
    for (int j = 0; j < 12; j++) {
        int i = tid + j * 256;
        int r = i / 24, c = i % 24;
        *(uint4*)&As[r * AST2 + c * 8] = *(const uint4*)(g_attn + (size_t)(m0 + r) * CDIM + c * 8);
    }

    for (int t = 0; t < 3; t++) {
        int n0 = t * 64;
        __syncthreads();
        #pragma unroll
        for (int j = 0; j < 6; j++) {      // raw fp16 B tile
            int i = tid + j * 256;
            int r = i / 24, c = i % 24;
            *(uint4*)&Bsh[r * AST2 + c * 8] =
                *(const uint4*)(g_wout_h + (size_t)(n0 + r) * CDIM + c * 8);
        }
        __syncthreads();

        float acc[2][4][4] = {};
        #pragma unroll
        for (int kk = 0; kk < 12; kk++) {
            uint32_t kb = (uint32_t)(kk * 32);
            uint32_t a0[4], a1[4], b0[4], b1[4];
            ldsm_x4(a0, aoff0 + kb);
            ldsm_x4(a1, aoff1 + kb);
            ldsm_x4(b0, boff0 + kb);
            ldsm_x4(b1, boff1 + kb);
            mma_f16(acc[0][0], a0, b0);     mma_f16(acc[0][1], a0, b0 + 2);
            mma_f16(acc[0][2], a0, b1);     mma_f16(acc[0][3], a0, b1 + 2);
            mma_f16(acc[1][0], a1, b0);     mma_f16(acc[1][1], a1, b0 + 2);
            mma_f16(acc[1][2], a1, b1);     mma_f16(acc[1][3], a1, b1 + 2);
        }

        #pragma unroll
        for (int mt = 0; mt < 2; mt++) {
            #pragma unroll
            for (int half = 0; half < 2; half++) {
                int m = m0 + warp_m + mt * 16 + lr + half * 8;
                int bb = m >> 16, y = (m >> 8) & 255, xx = m & 255;
                int yf = (y + DISP) & 255, xf = (xx + DISP) & 255;
                float* op = out + ((size_t)(bb * IMG + yf) * IMG + xf) * CDIM + n0 + warp_n;
                #pragma unroll
                for (int nt = 0; nt < 4; nt++) {
                    int col = nt * 8 + lc * 2;
                    float b0v = bout[n0 + warp_n + col];
                    float b1v = bout[n0 + warp_n + col + 1];
                    *(float2*)(op + col) = make_float2(acc[mt][nt][half * 2] + b0v,
                                                       acc[mt][nt][half * 2 + 1] + b1v);
                }
            }
        }
    }
}

// ---------------------------------------------------------------------------
extern "C" void kernel_launch(void* const* d_in, const int* in_sizes, int n_in,
                              void* d_out, int out_size) {
    const float* x    = (const float*)d_in[0];
    const float* wqkv = (const float*)d_in[1];
    const float* pos  = (const float*)d_in[2];
    const float* wout = (const float*)d_in[3];
    const float* bout = (const float*)d_in[4];
    float* out = (float*)d_out;

    cudaFuncSetAttribute(qkv_tc, cudaFuncAttributeMaxDynamicSharedMemorySize, SMEM_G);
    cudaFuncSetAttribute(out_tc, cudaFuncAttributeMaxDynamicSharedMemorySize, SMEM_G);

    bias_kernel<<<16, 256>>>(pos);
    wconv_kernel<<<(NQ * CDIM + 255) / 256, 256>>>(wqkv, wout);
    qkv_tc<<<MTOT / 128, 256, SMEM_G>>>(x);
    attn_mma<<<BATCH * NWIN * HEADS, 128>>>();
    out_tc<<<MTOT / 128, 256, SMEM_G>>>(bout, out);
}

// round 15
// speedup vs baseline: 1.3033x; 1.3033x over previous
#include <cuda_runtime.h>
#include <cuda_fp16.h>
#include <cstdint>

#define HEADS 6
#define HD 32
#define CDIM 192
#define NQ 576
#define DISP 4
#define IMG 256
#define BATCH 4
#define TOK 64
#define NWIN 1024
#define MTOT (BATCH * IMG * IMG)
#define ATT_SCALE 0.17677669529663687f

// scratch (allocation-free rule: __device__ globals) — fp16 intermediates
__device__ __half g_qkv[(size_t)MTOT * NQ];     // ROLLED coords, [m, 576]
__device__ __half g_attn[(size_t)MTOT * CDIM];  // ROLLED coords, [m, 192]
__device__ float g_bias[TOK * TOK];
__device__ __half g_wqkv_h[NQ * CDIM];          // fp16 weights (pre-converted)
__device__ __half g_wout_h[CDIM * CDIM];

// ---------------------------------------------------------------------------
// mma.sync / ldmatrix helpers (fp16, fp32 accumulate)
// ---------------------------------------------------------------------------
__device__ __forceinline__ void mma_f16(float* c, const uint32_t* a, const uint32_t* b) {
    asm volatile(
        "mma.sync.aligned.m16n8k16.row.col.f32.f16.f16.f32 "
        "{%0,%1,%2,%3}, {%4,%5,%6,%7}, {%8,%9}, {%0,%1,%2,%3};"
        : "+f"(c[0]), "+f"(c[1]), "+f"(c[2]), "+f"(c[3])
        : "r"(a[0]), "r"(a[1]), "r"(a[2]), "r"(a[3]), "r"(b[0]), "r"(b[1]));
}
__device__ __forceinline__ uint32_t smem_u32(const void* p) {
    uint32_t a;
    asm("{ .reg .u64 t; cvta.to.shared.u64 t, %1; cvt.u32.u64 %0, t; }" : "=r"(a) : "l"(p));
    return a;
}
__device__ __forceinline__ void ldsm_x4(uint32_t* r, uint32_t addr) {
    asm volatile("ldmatrix.sync.aligned.m8n8.x4.shared.b16 {%0,%1,%2,%3}, [%4];"
                 : "=r"(r[0]), "=r"(r[1]), "=r"(r[2]), "=r"(r[3]) : "r"(addr));
}
__device__ __forceinline__ void ldsm_x4_t(uint32_t* r, uint32_t addr) {
    asm volatile("ldmatrix.sync.aligned.m8n8.x4.trans.shared.b16 {%0,%1,%2,%3}, [%4];"
                 : "=r"(r[0]), "=r"(r[1]), "=r"(r[2]), "=r"(r[3]) : "r"(addr));
}
__device__ __forceinline__ uint32_t packh2(float a, float b) {
    __half2 h = __floats2half2_rn(a, b);
    return *reinterpret_cast<uint32_t*>(&h);
}

// GEMM smem: BM=64 rows A + 64 rows B, 200 halves/row (400B ≡ 16 mod 128 -> ldsm conflict-free)
#define AST2 200
#define A_H (64 * AST2)
#define SMEM_BYTES (2 * A_H * 2)   // 51200 B

// ---------------------------------------------------------------------------
// Kernel 0a: gather rel-pos bias table;  0b: weights fp32 -> fp16
// ---------------------------------------------------------------------------
__global__ void bias_kernel(const float* __restrict__ pos) {
    int idx = blockIdx.x * blockDim.x + threadIdx.x;
    if (idx < TOK * TOK) {
        int i = idx >> 6, j = idx & 63;
        g_bias[idx] = pos[((i >> 3) - (j >> 3) + 7) * 15 + ((i & 7) - (j & 7) + 7)];
    }
}
__global__ void wconv_kernel(const float* __restrict__ wqkv, const float* __restrict__ wout) {
    int idx = blockIdx.x * blockDim.x + threadIdx.x;
    if (idx < NQ * CDIM)   g_wqkv_h[idx] = __float2half_rn(wqkv[idx]);
    if (idx < CDIM * CDIM) g_wout_h[idx] = __float2half_rn(wout[idx]);
}

// ---------------------------------------------------------------------------
// Kernel 1: QKV GEMM (fp16 m16n8k16). BM=64, 128 thr, warp tile 32x32.
// B tiles: raw fp16 copies. Roll folded into A-load; g_qkv fp16, ROLLED coords.
// ---------------------------------------------------------------------------
__global__ __launch_bounds__(128, 4) void qkv_tc(const float* __restrict__ x) {
    extern __shared__ __half smh[];
    __half* As = smh;
    __half* Bsh = smh + A_H;
    uint32_t sbase = smem_u32(smh);
    uint32_t bbase = sbase + A_H * 2;

    int tid = threadIdx.x;
    int wid = tid >> 5, lane = tid & 31;
    int warp_m = (wid >> 1) * 32;
    int warp_n = (wid & 1) * 32;
    int lr = lane >> 2, lc = lane & 3;
    int m0 = blockIdx.x * 64;

    uint32_t aoff0 = sbase + (uint32_t)((warp_m + (lane & 7) + ((lane >> 3) & 1) * 8) * (AST2 * 2)
                                        + ((lane >> 4) & 1) * 16);
    uint32_t aoff1 = aoff0 + 16 * (AST2 * 2);
    uint32_t boff0 = bbase + (uint32_t)((warp_n + (lane & 7) + ((lane >> 4) & 1) * 8) * (AST2 * 2)
                                        + ((lane >> 3) & 1) * 16);
    uint32_t boff1 = boff0 + 16 * (AST2 * 2);

    // A tile 64x192 fp32 -> fp16, roll folded in. 3072 float4 / 128 thr.
    #pragma unroll
    for (int j = 0; j < 24; j++) {
        int i = tid + j * 128;
        int r = i / 48, c4 = i % 48;
        int m = m0 + r;
        int bb = m >> 16, y = (m >> 8) & 255, xx = m & 255;
        int ys = (y + DISP) & 255, xs = (xx + DISP) & 255;
        float4 v = *(const float4*)(x + ((size_t)((bb * IMG + ys) * IMG + xs)) * CDIM + c4 * 4);
        *(__half2*)&As[r * AST2 + c4 * 4]     = __floats2half2_rn(v.x, v.y);
        *(__half2*)&As[r * AST2 + c4 * 4 + 2] = __floats2half2_rn(v.z, v.w);
    }

    for (int t = 0; t < 9; t++) {
        int n0 = t * 64;
        __syncthreads();   // prev-tile readers done (covers A-load on t=0 too)
        #pragma unroll
        for (int j = 0; j < 12; j++) {       // 64 rows x 24 16B-chunks, raw fp16
            int i = tid + j * 128;
            int r = i / 24, c = i % 24;
            *(uint4*)&Bsh[r * AST2 + c * 8] =
                *(const uint4*)(g_wqkv_h + (size_t)(n0 + r) * CDIM + c * 8);
        }
        __syncthreads();

        float acc[2][4][4] = {};
        #pragma unroll
        for (int kk = 0; kk < 12; kk++) {        // K=192 in k16 steps
            uint32_t kb = (uint32_t)(kk * 32);   // 16 halves
            uint32_t a0[4], a1[4], b0[4], b1[4];
            ldsm_x4(a0, aoff0 + kb);
            ldsm_x4(a1, aoff1 + kb);
            ldsm_x4(b0, boff0 + kb);
            ldsm_x4(b1, boff1 + kb);
            mma_f16(acc[0][0], a0, b0);     mma_f16(acc[0][1], a0, b0 + 2);
            mma_f16(acc[0][2], a0, b1);     mma_f16(acc[0][3], a0, b1 + 2);
            mma_f16(acc[1][0], a1, b0);     mma_f16(acc[1][1], a1, b0 + 2);
            mma_f16(acc[1][2], a1, b1);     mma_f16(acc[1][3], a1, b1 + 2);
        }

        // Epilogue: fp16 stores, natural [m][576] layout.
        #pragma unroll
        for (int mt = 0; mt < 2; mt++) {
            size_t r0 = (size_t)(m0 + warp_m + mt * 16 + lr) * NQ + n0 + warp_n;
            size_t r1 = r0 + 8 * NQ;
            #pragma unroll
            for (int nt = 0; nt < 4; nt++) {
                int col = nt * 8 + lc * 2;
                *(__half2*)(g_qkv + r0 + col) = __floats2half2_rn(acc[mt][nt][0], acc[mt][nt][1]);
                *(__half2*)(g_qkv + r1 + col) = __floats2half2_rn(acc[mt][nt][2], acc[mt][nt][3]);
            }
        }
    }
}

// ---------------------------------------------------------------------------
// Kernel 2: windowed attention, fp16 MMA. Block = (b, win, head), 128 thr.
// Bias staged through smem (round-12 style); P converted C-frag -> A-frag
// IN REGISTERS (round-13 win kept).
// ---------------------------------------------------------------------------
#define QST2 40    // Q/K/V row stride (halves): 80B ≡ 16 mod 128 -> conflict-free
#define BST 68     // bias row stride (fp32 words), float4-aligned, conflict-free

__global__ __launch_bounds__(128) void attn_mma() {
    __shared__ __half qkvs[3 * 64 * QST2];  // Q | K | V, each [64][40]
    __shared__ float bsm[64 * BST];         // bias [64][68]

    int bid = blockIdx.x;
    int head = bid % HEADS;
    int t2 = bid / HEADS;
    int win = t2 & (NWIN - 1);
    int bb = t2 >> 10;
    int wy = win >> 5, wx = win & 31;

    int tid = threadIdx.x;
    int wid = tid >> 5, lane = tid & 31;
    int lr = lane >> 2, lc = lane & 3;
    int r_base = wid * 16;

    uint32_t qbase = smem_u32(qkvs);
    uint32_t kbase = qbase + 64 * QST2 * 2;
    uint32_t vbase = kbase + 64 * QST2 * 2;

    // ---- load Q,K,V (fp16 raw 16B chunks) + bias (coalesced to smem) ----
    #pragma unroll
    for (int l = 0; l < 6; l++) {
        int idx = tid + l * 128;            // 768 = 3 tensors x 64 tok x 4 chunks
        int tsel = idx >> 8;
        int rem = idx & 255;
        int j = rem >> 2, c = rem & 3;
        int y = wy * 8 + (j >> 3), xx = wx * 8 + (j & 7);
        size_t base = ((size_t)((bb * IMG + y) * IMG + xx)) * NQ + tsel * CDIM + head * HD + c * 8;
        *(uint4*)&qkvs[tsel * 64 * QST2 + j * QST2 + c * 8] = *(const uint4*)(g_qkv + base);
    }
    #pragma unroll
    for (int l = 0; l < 8; l++) {
        int w0 = (tid + l * 128) * 4;
        int row = w0 >> 6, col = w0 & 63;
        *(float4*)(bsm + row * BST + col) = *(const float4*)(g_bias + w0);
    }
    __syncthreads();

    // ---- S = Q K^T * scale + bias ----
    uint32_t qoff = qbase + (uint32_t)((r_base + (lane & 7) + ((lane >> 3) & 1) * 8) * (QST2 * 2)
                                       + ((lane >> 4) & 1) * 16);
    uint32_t qa[2][4];
    ldsm_x4(qa[0], qoff);
    ldsm_x4(qa[1], qoff + 32);

    float s[8][4] = {};
    #pragma unroll
    for (int p = 0; p < 4; p++) {          // nt pairs (16 kv tokens each)
        uint32_t koff = kbase + (uint32_t)((p * 16 + (lane & 7) + ((lane >> 4) & 1) * 8) * (QST2 * 2)
                                           + ((lane >> 3) & 1) * 16);
        #pragma unroll
        for (int kk = 0; kk < 2; kk++) {
            uint32_t kb[4];
            ldsm_x4(kb, koff + kk * 32);
            mma_f16(s[2 * p],     qa[kk], kb);
            mma_f16(s[2 * p + 1], qa[kk], kb + 2);
        }
    }

    int row0 = r_base + lr, row1 = r_base + lr + 8;
    #pragma unroll
    for (int nt = 0; nt < 8; nt++) {
        int col = nt * 8 + lc * 2;
        float2 b0 = *(const float2*)(bsm + row0 * BST + col);
        float2 b1 = *(const float2*)(bsm + row1 * BST + col);
        s[nt][0] = s[nt][0] * ATT_SCALE + b0.x;
        s[nt][1] = s[nt][1] * ATT_SCALE + b0.y;
        s[nt][2] = s[nt][2] * ATT_SCALE + b1.x;
        s[nt][3] = s[nt][3] * ATT_SCALE + b1.y;
    }

    // ---- softmax (rows row0/row1; reduce across quad lanes) ----
    float mx0 = -1e30f, mx1 = -1e30f;
    #pragma unroll
    for (int nt = 0; nt < 8; nt++) {
        mx0 = fmaxf(mx0, fmaxf(s[nt][0], s[nt][1]));
        mx1 = fmaxf(mx1, fmaxf(s[nt][2], s[nt][3]));
    }
    mx0 = fmaxf(mx0, __shfl_xor_sync(0xffffffff, mx0, 1));
    mx0 = fmaxf(mx0, __shfl_xor_sync(0xffffffff, mx0, 2));
    mx1 = fmaxf(mx1, __shfl_xor_sync(0xffffffff, mx1, 1));
    mx1 = fmaxf(mx1, __shfl_xor_sync(0xffffffff, mx1, 2));
    float sum0 = 0.f, sum1 = 0.f;
    #pragma unroll
    for (int nt = 0; nt < 8; nt++) {
        s[nt][0] = __expf(s[nt][0] - mx0); sum0 += s[nt][0];
        s[nt][1] = __expf(s[nt][1] - mx0); sum0 += s[nt][1];
        s[nt][2] = __expf(s[nt][2] - mx1); sum1 += s[nt][2];
        s[nt][3] = __expf(s[nt][3] - mx1); sum1 += s[nt][3];
    }
    sum0 += __shfl_xor_sync(0xffffffff, sum0, 1);
    sum0 += __shfl_xor_sync(0xffffffff, sum0, 2);
    sum1 += __shfl_xor_sync(0xffffffff, sum1, 1);
    sum1 += __shfl_xor_sync(0xffffffff, sum1, 2);
    float inv0 = 1.f / sum0, inv1 = 1.f / sum1;

    // ---- O = P V: P built in registers (C-frag == A-frag layout) ----
    float o[4][4] = {};
    #pragma unroll
    for (int kk = 0; kk < 4; kk++) {       // 16 kv tokens per step
        uint32_t pa[4];
        pa[0] = packh2(s[2 * kk][0],     s[2 * kk][1]);
        pa[1] = packh2(s[2 * kk][2],     s[2 * kk][3]);
        pa[2] = packh2(s[2 * kk + 1][0], s[2 * kk + 1][1]);
        pa[3] = packh2(s[2 * kk + 1][2], s[2 * kk + 1][3]);
        #pragma unroll
        for (int q = 0; q < 2; q++) {      // n blocks of 16 (d-cols)
            uint32_t voff = vbase + (uint32_t)((kk * 16 + (lane & 7) + ((lane >> 3) & 1) * 8) * (QST2 * 2)
                                               + (q * 16 + ((lane >> 4) & 1) * 8) * 2);
            uint32_t vb[4];
            ldsm_x4_t(vb, voff);
            mma_f16(o[2 * q],     pa, vb);
            mma_f16(o[2 * q + 1], pa, vb + 2);
        }
    }

    // ---- epilogue: scale by 1/sum, write g_attn fp16 (rolled coords) ----
    {
        int i0 = r_base + lr;
        int y0 = wy * 8 + (i0 >> 3), x0 = wx * 8 + (i0 & 7);
        int i1 = i0 + 8;
        int y1 = wy * 8 + (i1 >> 3), x1 = wx * 8 + (i1 & 7);
        __half* p0 = g_attn + ((size_t)((bb * IMG + y0) * IMG + x0)) * CDIM + head * HD;
        __half* p1 = g_attn + ((size_t)((bb * IMG + y1) * IMG + x1)) * CDIM + head * HD;
        #pragma unroll
        for (int nt = 0; nt < 4; nt++) {
            int col = nt * 8 + lc * 2;
            *(__half2*)(p0 + col) = __floats2half2_rn(o[nt][0] * inv0, o[nt][1] * inv0);
            *(__half2*)(p1 + col) = __floats2half2_rn(o[nt][2] * inv1, o[nt][3] * inv1);
        }
    }
}

// ---------------------------------------------------------------------------
// Kernel 3: output projection (fp16 MMA) + bias; roll-back on store.
// BM=64, 128 thr (round-12 shape). Output fp32.
// ---------------------------------------------------------------------------
__global__ __launch_bounds__(128, 4) void out_tc(const float* __restrict__ bout,
                                                 float* __restrict__ out) {
    extern __shared__ __half smh[];
    __half* As = smh;
    __half* Bsh = smh + A_H;
    uint32_t sbase = smem_u32(smh);
    uint32_t bbase = sbase + A_H * 2;

    int tid = threadIdx.x;
    int wid = tid >> 5, lane = tid & 31;
    int warp_m = (wid >> 1) * 32;
    int warp_n = (wid & 1) * 32;
    int lr = lane >> 2, lc = lane & 3;
    int m0 = blockIdx.x * 64;

    uint32_t aoff0 = sbase + (uint32_t)((warp_m + (lane & 7) + ((lane >> 3) & 1) * 8) * (AST2 * 2)
                                        + ((lane >> 4) & 1) * 16);
    uint32_t aoff1 = aoff0 + 16 * (AST2 * 2);
    uint32_t boff0 = bbase + (uint32_t)((warp_n + (lane & 7) + ((lane >> 4) & 1) * 8) * (AST2 * 2)
                                        + ((lane >> 3) & 1) * 16);
    uint32_t boff1 = boff0 + 16 * (AST2 * 2);

    // A tile: raw fp16 16B copies.
    #pragma unroll
    for (int j = 0; j < 12; j++) {
        int i = tid + j * 128;
        int r = i / 24, c = i % 24;
        *(uint4*)&As[r * AST2 + c * 8] = *(const uint4*)(g_attn + (size_t)(m0 + r) * CDIM + c * 8);
    }

    for (int t = 0; t < 3; t++) {
        int n0 = t * 64;
        __syncthreads();
        #pragma unroll
        for (int j = 0; j < 12; j++) {     // raw fp16 B tile
            int i = tid + j * 128;
            int r = i / 24, c = i % 24;
            *(uint4*)&Bsh[r * AST2 + c * 8] =
                *(const uint4*)(g_wout_h + (size_t)(n0 + r) * CDIM + c * 8);
        }
        __syncthreads();

        float acc[2][4][4] = {};
        #pragma unroll
        for (int kk = 0; kk < 12; kk++) {
            uint32_t kb = (uint32_t)(kk * 32);
            uint32_t a0[4], a1[4], b0[4], b1[4];
            ldsm_x4(a0, aoff0 + kb);
            ldsm_x4(a1, aoff1 + kb);
            ldsm_x4(b0, boff0 + kb);
            ldsm_x4(b1, boff1 + kb);
            mma_f16(acc[0][0], a0, b0);     mma_f16(acc[0][1], a0, b0 + 2);
            mma_f16(acc[0][2], a0, b1);     mma_f16(acc[0][3], a0, b1 + 2);
            mma_f16(acc[1][0], a1, b0);     mma_f16(acc[1][1], a1, b0 + 2);
            mma_f16(acc[1][2], a1, b1);     mma_f16(acc[1][3], a1, b1 + 2);
        }

        #pragma unroll
        for (int mt = 0; mt < 2; mt++) {
            #pragma unroll
            for (int half = 0; half < 2; half++) {
                int m = m0 + warp_m + mt * 16 + lr + half * 8;
                int bb = m >> 16, y = (m >> 8) & 255, xx = m & 255;
                int yf = (y + DISP) & 255, xf = (xx + DISP) & 255;
                float* op = out + ((size_t)(bb * IMG + yf) * IMG + xf) * CDIM + n0 + warp_n;
                #pragma unroll
                for (int nt = 0; nt < 4; nt++) {
                    int col = nt * 8 + lc * 2;
                    float b0v = bout[n0 + warp_n + col];
                    float b1v = bout[n0 + warp_n + col + 1];
                    *(float2*)(op + col) = make_float2(acc[mt][nt][half * 2] + b0v,
                                                       acc[mt][nt][half * 2 + 1] + b1v);
                }
            }
        }
    }
}

// ---------------------------------------------------------------------------
extern "C" void kernel_launch(void* const* d_in, const int* in_sizes, int n_in,
                              void* d_out, int out_size) {
    const float* x    = (const float*)d_in[0];
    const float* wqkv = (const float*)d_in[1];
    const float* pos  = (const float*)d_in[2];
    const float* wout = (const float*)d_in[3];
    const float* bout = (const float*)d_in[4];
    float* out = (float*)d_out;

    cudaFuncSetAttribute(qkv_tc, cudaFuncAttributeMaxDynamicSharedMemorySize, SMEM_BYTES);
    cudaFuncSetAttribute(out_tc, cudaFuncAttributeMaxDynamicSharedMemorySize, SMEM_BYTES);

    bias_kernel<<<16, 256>>>(pos);
    wconv_kernel<<<(NQ * CDIM + 255) / 256, 256>>>(wqkv, wout);
    qkv_tc<<<MTOT / 64, 128, SMEM_BYTES>>>(x);
    attn_mma<<<BATCH * NWIN * HEADS, 128>>>();
    out_tc<<<MTOT / 64, 128, SMEM_BYTES>>>(bout, out);
}

// round 16
// speedup vs baseline: 1.4047x; 1.0778x over previous
#include <cuda_runtime.h>
#include <cuda_fp16.h>
#include <cstdint>

#define HEADS 6
#define HD 32
#define CDIM 192
#define NQ 576
#define DISP 4
#define IMG 256
#define BATCH 4
#define TOK 64
#define NWIN 1024
#define MTOT (BATCH * IMG * IMG)
#define ATT_SCALE 0.17677669529663687f

// scratch (allocation-free rule: __device__ globals) — fp16 intermediates
__device__ __half g_qkv[(size_t)MTOT * NQ];     // ROLLED coords, [m, 576]
__device__ __half g_attn[(size_t)MTOT * CDIM];  // ROLLED coords, [m, 192]
__device__ float g_bias[TOK * TOK];
__device__ __half g_wqkv_h[NQ * CDIM];          // fp16 weights (pre-converted)
__device__ __half g_wout_h[CDIM * CDIM];

// ---------------------------------------------------------------------------
// mma.sync / ldmatrix helpers (fp16, fp32 accumulate)
// ---------------------------------------------------------------------------
__device__ __forceinline__ void mma_f16(float* c, const uint32_t* a, const uint32_t* b) {
    asm volatile(
        "mma.sync.aligned.m16n8k16.row.col.f32.f16.f16.f32 "
        "{%0,%1,%2,%3}, {%4,%5,%6,%7}, {%8,%9}, {%0,%1,%2,%3};"
        : "+f"(c[0]), "+f"(c[1]), "+f"(c[2]), "+f"(c[3])
        : "r"(a[0]), "r"(a[1]), "r"(a[2]), "r"(a[3]), "r"(b[0]), "r"(b[1]));
}
__device__ __forceinline__ uint32_t smem_u32(const void* p) {
    uint32_t a;
    asm("{ .reg .u64 t; cvta.to.shared.u64 t, %1; cvt.u32.u64 %0, t; }" : "=r"(a) : "l"(p));
    return a;
}
__device__ __forceinline__ void ldsm_x4(uint32_t* r, uint32_t addr) {
    asm volatile("ldmatrix.sync.aligned.m8n8.x4.shared.b16 {%0,%1,%2,%3}, [%4];"
                 : "=r"(r[0]), "=r"(r[1]), "=r"(r[2]), "=r"(r[3]) : "r"(addr));
}
__device__ __forceinline__ void ldsm_x4_t(uint32_t* r, uint32_t addr) {
    asm volatile("ldmatrix.sync.aligned.m8n8.x4.trans.shared.b16 {%0,%1,%2,%3}, [%4];"
                 : "=r"(r[0]), "=r"(r[1]), "=r"(r[2]), "=r"(r[3]) : "r"(addr));
}
__device__ __forceinline__ uint32_t packh2(float a, float b) {
    __half2 h = __floats2half2_rn(a, b);
    return *reinterpret_cast<uint32_t*>(&h);
}

// GEMM smem: BM=64 rows A + 64 rows B, 200 halves/row (400B ≡ 16 mod 128 -> ldsm conflict-free)
#define AST2 200
#define A_H (64 * AST2)
#define SMEM_BYTES (2 * A_H * 2)   // 51200 B

// ---------------------------------------------------------------------------
// Kernel 0a: gather rel-pos bias table;  0b: weights fp32 -> fp16
// ---------------------------------------------------------------------------
__global__ void bias_kernel(const float* __restrict__ pos) {
    int idx = blockIdx.x * blockDim.x + threadIdx.x;
    if (idx < TOK * TOK) {
        int i = idx >> 6, j = idx & 63;
        g_bias[idx] = pos[((i >> 3) - (j >> 3) + 7) * 15 + ((i & 7) - (j & 7) + 7)];
    }
}
__global__ void wconv_kernel(const float* __restrict__ wqkv, const float* __restrict__ wout) {
    int idx = blockIdx.x * blockDim.x + threadIdx.x;
    if (idx < NQ * CDIM)   g_wqkv_h[idx] = __float2half_rn(wqkv[idx]);
    if (idx < CDIM * CDIM) g_wout_h[idx] = __float2half_rn(wout[idx]);
}

// ---------------------------------------------------------------------------
// Kernel 1: QKV GEMM (fp16 m16n8k16). BM=64, 128 thr, warp tile 32x32.
// B tiles: raw fp16 copies. Roll folded into A-load; g_qkv fp16, ROLLED coords.
// ---------------------------------------------------------------------------
__global__ __launch_bounds__(128, 4) void qkv_tc(const float* __restrict__ x) {
    extern __shared__ __half smh[];
    __half* As = smh;
    __half* Bsh = smh + A_H;
    uint32_t sbase = smem_u32(smh);
    uint32_t bbase = sbase + A_H * 2;

    int tid = threadIdx.x;
    int wid = tid >> 5, lane = tid & 31;
    int warp_m = (wid >> 1) * 32;
    int warp_n = (wid & 1) * 32;
    int lr = lane >> 2, lc = lane & 3;
    int m0 = blockIdx.x * 64;

    uint32_t aoff0 = sbase + (uint32_t)((warp_m + (lane & 7) + ((lane >> 3) & 1) * 8) * (AST2 * 2)
                                        + ((lane >> 4) & 1) * 16);
    uint32_t aoff1 = aoff0 + 16 * (AST2 * 2);
    uint32_t boff0 = bbase + (uint32_t)((warp_n + (lane & 7) + ((lane >> 4) & 1) * 8) * (AST2 * 2)
                                        + ((lane >> 3) & 1) * 16);
    uint32_t boff1 = boff0 + 16 * (AST2 * 2);

    // A tile 64x192 fp32 -> fp16, roll folded in. 3072 float4 / 128 thr.
    #pragma unroll
    for (int j = 0; j < 24; j++) {
        int i = tid + j * 128;
        int r = i / 48, c4 = i % 48;
        int m = m0 + r;
        int bb = m >> 16, y = (m >> 8) & 255, xx = m & 255;
        int ys = (y + DISP) & 255, xs = (xx + DISP) & 255;
        float4 v = *(const float4*)(x + ((size_t)((bb * IMG + ys) * IMG + xs)) * CDIM + c4 * 4);
        *(__half2*)&As[r * AST2 + c4 * 4]     = __floats2half2_rn(v.x, v.y);
        *(__half2*)&As[r * AST2 + c4 * 4 + 2] = __floats2half2_rn(v.z, v.w);
    }

    for (int t = 0; t < 9; t++) {
        int n0 = t * 64;
        __syncthreads();   // prev-tile readers done (covers A-load on t=0 too)
        #pragma unroll
        for (int j = 0; j < 12; j++) {       // 64 rows x 24 16B-chunks, raw fp16
            int i = tid + j * 128;
            int r = i / 24, c = i % 24;
            *(uint4*)&Bsh[r * AST2 + c * 8] =
                *(const uint4*)(g_wqkv_h + (size_t)(n0 + r) * CDIM + c * 8);
        }
        __syncthreads();

        float acc[2][4][4] = {};
        #pragma unroll
        for (int kk = 0; kk < 12; kk++) {        // K=192 in k16 steps
            uint32_t kb = (uint32_t)(kk * 32);   // 16 halves
            uint32_t a0[4], a1[4], b0[4], b1[4];
            ldsm_x4(a0, aoff0 + kb);
            ldsm_x4(a1, aoff1 + kb);
            ldsm_x4(b0, boff0 + kb);
            ldsm_x4(b1, boff1 + kb);
            mma_f16(acc[0][0], a0, b0);     mma_f16(acc[0][1], a0, b0 + 2);
            mma_f16(acc[0][2], a0, b1);     mma_f16(acc[0][3], a0, b1 + 2);
            mma_f16(acc[1][0], a1, b0);     mma_f16(acc[1][1], a1, b0 + 2);
            mma_f16(acc[1][2], a1, b1);     mma_f16(acc[1][3], a1, b1 + 2);
        }

        // Epilogue: fp16 stores, natural [m][576] layout.
        #pragma unroll
        for (int mt = 0; mt < 2; mt++) {
            size_t r0 = (size_t)(m0 + warp_m + mt * 16 + lr) * NQ + n0 + warp_n;
            size_t r1 = r0 + 8 * NQ;
            #pragma unroll
            for (int nt = 0; nt < 4; nt++) {
                int col = nt * 8 + lc * 2;
                *(__half2*)(g_qkv + r0 + col) = __floats2half2_rn(acc[mt][nt][0], acc[mt][nt][1]);
                *(__half2*)(g_qkv + r1 + col) = __floats2half2_rn(acc[mt][nt][2], acc[mt][nt][3]);
            }
        }
    }
}

// ---------------------------------------------------------------------------
// Kernel 2: windowed attention, fp16 MMA. Block = (b, win, head-triple),
// 384 thr = 12 warps = 3 heads x 4 row-warps. Bias staged ONCE per 3 heads;
// Q/K/V gather is 192B-contiguous per (token, tensor). In-register P.
// ---------------------------------------------------------------------------
#define QST2 40    // Q/K/V row stride (halves): 80B ≡ 16 mod 128 -> conflict-free
#define BST 68     // bias row stride (fp32 words), float4-aligned, conflict-free
#define ATTN_SMEM (9 * 64 * QST2 * 2 + 64 * BST * 4)   // 46080 + 17408 = 63488 B

__global__ __launch_bounds__(384, 2) void attn_mma() {
    extern __shared__ __half ash[];
    __half* qkvs = ash;                         // [3 heads][3 tensors][64][QST2]
    float* bsm = (float*)(ash + 9 * 64 * QST2); // bias [64][68]

    int bid = blockIdx.x;
    int hbase = (bid & 1) * 3;      // head triple: 0-2 or 3-5
    int t2 = bid >> 1;
    int win = t2 & (NWIN - 1);
    int bb = t2 >> 10;
    int wy = win >> 5, wx = win & 31;

    int tid = threadIdx.x;
    int wid = tid >> 5, lane = tid & 31;
    int lr = lane >> 2, lc = lane & 3;
    int head_l = wid >> 2;          // 0..2 local head
    int r_base = (wid & 3) * 16;    // q-row block within head

    // ---- gather Q,K,V for 3 heads (contiguous 192B runs) ----
    // 64 tokens x 36 chunks (3 tensors x 3 heads x 4 x 16B) = 2304 / 384 thr.
    #pragma unroll
    for (int l = 0; l < 6; l++) {
        int idx = tid + l * 384;
        int j = idx / 36, c = idx % 36;
        int tensor = c / 12;
        int hc = c % 12;
        int hl = hc >> 2, cc = hc & 3;
        int y = wy * 8 + (j >> 3), xx = wx * 8 + (j & 7);
        size_t src = ((size_t)((bb * IMG + y) * IMG + xx)) * NQ
                     + tensor * CDIM + (hbase + hl) * HD + cc * 8;
        *(uint4*)&qkvs[((hl * 3 + tensor) * 64 + j) * QST2 + cc * 8] =
            *(const uint4*)(g_qkv + src);
    }
    // ---- bias staged once per block ----
    #pragma unroll
    for (int l = 0; l < 3; l++) {
        int idx = tid + l * 384;
        if (idx < 1024) {
            int w0 = idx * 4;
            int row = w0 >> 6, col = w0 & 63;
            *(float4*)(bsm + row * BST + col) = *(const float4*)(g_bias + w0);
        }
    }
    __syncthreads();

    uint32_t hb = smem_u32(qkvs) + (uint32_t)(head_l * 3 * 64 * QST2 * 2);
    uint32_t qbase = hb;
    uint32_t kbase = hb + 64 * QST2 * 2;
    uint32_t vbase = kbase + 64 * QST2 * 2;

    // ---- S = Q K^T * scale + bias ----
    uint32_t qoff = qbase + (uint32_t)((r_base + (lane & 7) + ((lane >> 3) & 1) * 8) * (QST2 * 2)
                                       + ((lane >> 4) & 1) * 16);
    uint32_t qa[2][4];
    ldsm_x4(qa[0], qoff);
    ldsm_x4(qa[1], qoff + 32);

    float s[8][4] = {};
    #pragma unroll
    for (int p = 0; p < 4; p++) {          // nt pairs (16 kv tokens each)
        uint32_t koff = kbase + (uint32_t)((p * 16 + (lane & 7) + ((lane >> 4) & 1) * 8) * (QST2 * 2)
                                           + ((lane >> 3) & 1) * 16);
        #pragma unroll
        for (int kk = 0; kk < 2; kk++) {
            uint32_t kb[4];
            ldsm_x4(kb, koff + kk * 32);
            mma_f16(s[2 * p],     qa[kk], kb);
            mma_f16(s[2 * p + 1], qa[kk], kb + 2);
        }
    }

    int row0 = r_base + lr, row1 = r_base + lr + 8;
    #pragma unroll
    for (int nt = 0; nt < 8; nt++) {
        int col = nt * 8 + lc * 2;
        float2 b0 = *(const float2*)(bsm + row0 * BST + col);
        float2 b1 = *(const float2*)(bsm + row1 * BST + col);
        s[nt][0] = s[nt][0] * ATT_SCALE + b0.x;
        s[nt][1] = s[nt][1] * ATT_SCALE + b0.y;
        s[nt][2] = s[nt][2] * ATT_SCALE + b1.x;
        s[nt][3] = s[nt][3] * ATT_SCALE + b1.y;
    }

    // ---- softmax (rows row0/row1; reduce across quad lanes) ----
    float mx0 = -1e30f, mx1 = -1e30f;
    #pragma unroll
    for (int nt = 0; nt < 8; nt++) {
        mx0 = fmaxf(mx0, fmaxf(s[nt][0], s[nt][1]));
        mx1 = fmaxf(mx1, fmaxf(s[nt][2], s[nt][3]));
    }
    mx0 = fmaxf(mx0, __shfl_xor_sync(0xffffffff, mx0, 1));
    mx0 = fmaxf(mx0, __shfl_xor_sync(0xffffffff, mx0, 2));
    mx1 = fmaxf(mx1, __shfl_xor_sync(0xffffffff, mx1, 1));
    mx1 = fmaxf(mx1, __shfl_xor_sync(0xffffffff, mx1, 2));
    float sum0 = 0.f, sum1 = 0.f;
    #pragma unroll
    for (int nt = 0; nt < 8; nt++) {
        s[nt][0] = __expf(s[nt][0] - mx0); sum0 += s[nt][0];
        s[nt][1] = __expf(s[nt][1] - mx0); sum0 += s[nt][1];
        s[nt][2] = __expf(s[nt][2] - mx1); sum1 += s[nt][2];
        s[nt][3] = __expf(s[nt][3] - mx1); sum1 += s[nt][3];
    }
    sum0 += __shfl_xor_sync(0xffffffff, sum0, 1);
    sum0 += __shfl_xor_sync(0xffffffff, sum0, 2);
    sum1 += __shfl_xor_sync(0xffffffff, sum1, 1);
    sum1 += __shfl_xor_sync(0xffffffff, sum1, 2);
    float inv0 = 1.f / sum0, inv1 = 1.f / sum1;

    // ---- O = P V: P built in registers (C-frag == A-frag layout) ----
    float o[4][4] = {};
    #pragma unroll
    for (int kk = 0; kk < 4; kk++) {       // 16 kv tokens per step
        uint32_t pa[4];
        pa[0] = packh2(s[2 * kk][0],     s[2 * kk][1]);
        pa[1] = packh2(s[2 * kk][2],     s[2 * kk][3]);
        pa[2] = packh2(s[2 * kk + 1][0], s[2 * kk + 1][1]);
        pa[3] = packh2(s[2 * kk + 1][2], s[2 * kk + 1][3]);
        #pragma unroll
        for (int q = 0; q < 2; q++) {      // n blocks of 16 (d-cols)
            uint32_t voff = vbase + (uint32_t)((kk * 16 + (lane & 7) + ((lane >> 3) & 1) * 8) * (QST2 * 2)
                                               + (q * 16 + ((lane >> 4) & 1) * 8) * 2);
            uint32_t vb[4];
            ldsm_x4_t(vb, voff);
            mma_f16(o[2 * q],     pa, vb);
            mma_f16(o[2 * q + 1], pa, vb + 2);
        }
    }

    // ---- epilogue: scale by 1/sum, write g_attn fp16 (rolled coords) ----
    {
        int head = hbase + head_l;
        int i0 = r_base + lr;
        int y0 = wy * 8 + (i0 >> 3), x0 = wx * 8 + (i0 & 7);
        int i1 = i0 + 8;
        int y1 = wy * 8 + (i1 >> 3), x1 = wx * 8 + (i1 & 7);
        __half* p0 = g_attn + ((size_t)((bb * IMG + y0) * IMG + x0)) * CDIM + head * HD;
        __half* p1 = g_attn + ((size_t)((bb * IMG + y1) * IMG + x1)) * CDIM + head * HD;
        #pragma unroll
        for (int nt = 0; nt < 4; nt++) {
            int col = nt * 8 + lc * 2;
            *(__half2*)(p0 + col) = __floats2half2_rn(o[nt][0] * inv0, o[nt][1] * inv0);
            *(__half2*)(p1 + col) = __floats2half2_rn(o[nt][2] * inv1, o[nt][3] * inv1);
        }
    }
}

// ---------------------------------------------------------------------------
// Kernel 3: output projection (fp16 MMA) + bias; roll-back on store.
// BM=64, 128 thr. Output fp32.
// ---------------------------------------------------------------------------
__global__ __launch_bounds__(128, 4) void out_tc(const float* __restrict__ bout,
                                                 float* __restrict__ out) {
    extern __shared__ __half smh[];
    __half* As = smh;
    __half* Bsh = smh + A_H;
    uint32_t sbase = smem_u32(smh);
    uint32_t bbase = sbase + A_H * 2;

    int tid = threadIdx.x;
    int wid = tid >> 5, lane = tid & 31;
    int warp_m = (wid >> 1) * 32;
    int warp_n = (wid & 1) * 32;
    int lr = lane >> 2, lc = lane & 3;
    int m0 = blockIdx.x * 64;

    uint32_t aoff0 = sbase + (uint32_t)((warp_m + (lane & 7) + ((lane >> 3) & 1) * 8) * (AST2 * 2)
                                        + ((lane >> 4) & 1) * 16);
    uint32_t aoff1 = aoff0 + 16 * (AST2 * 2);
    uint32_t boff0 = bbase + (uint32_t)((warp_n + (lane & 7) + ((lane >> 4) & 1) * 8) * (AST2 * 2)
                                        + ((lane >> 3) & 1) * 16);
    uint32_t boff1 = boff0 + 16 * (AST2 * 2);

    // A tile: raw fp16 16B copies.
    #pragma unroll
    for (int j = 0; j < 12; j++) {
        int i = tid + j * 128;
        int r = i / 24, c = i % 24;
        *(uint4*)&As[r * AST2 + c * 8] = *(const uint4*)(g_attn + (size_t)(m0 + r) * CDIM + c * 8);
    }

    for (int t = 0; t < 3; t++) {
        int n0 = t * 64;
        __syncthreads();
        #pragma unroll
        for (int j = 0; j < 12; j++) {     // raw fp16 B tile
            int i = tid + j * 128;
            int r = i / 24, c = i % 24;
            *(uint4*)&Bsh[r * AST2 + c * 8] =
                *(const uint4*)(g_wout_h + (size_t)(n0 + r) * CDIM + c * 8);
        }
        __syncthreads();

        float acc[2][4][4] = {};
        #pragma unroll
        for (int kk = 0; kk < 12; kk++) {
            uint32_t kb = (uint32_t)(kk * 32);
            uint32_t a0[4], a1[4], b0[4], b1[4];
            ldsm_x4(a0, aoff0 + kb);
            ldsm_x4(a1, aoff1 + kb);
            ldsm_x4(b0, boff0 + kb);
            ldsm_x4(b1, boff1 + kb);
            mma_f16(acc[0][0], a0, b0);     mma_f16(acc[0][1], a0, b0 + 2);
            mma_f16(acc[0][2], a0, b1);     mma_f16(acc[0][3], a0, b1 + 2);
            mma_f16(acc[1][0], a1, b0);     mma_f16(acc[1][1], a1, b0 + 2);
            mma_f16(acc[1][2], a1, b1);     mma_f16(acc[1][3], a1, b1 + 2);
        }

        #pragma unroll
        for (int mt = 0; mt < 2; mt++) {
            #pragma unroll
            for (int half = 0; half < 2; half++) {
                int m = m0 + warp_m + mt * 16 + lr + half * 8;
                int bb = m >> 16, y = (m >> 8) & 255, xx = m & 255;
                int yf = (y + DISP) & 255, xf = (xx + DISP) & 255;
                float* op = out + ((size_t)(bb * IMG + yf) * IMG + xf) * CDIM + n0 + warp_n;
                #pragma unroll
                for (int nt = 0; nt < 4; nt++) {
                    int col = nt * 8 + lc * 2;
                    float b0v = bout[n0 + warp_n + col];
                    float b1v = bout[n0 + warp_n + col + 1];
                    *(float2*)(op + col) = make_float2(acc[mt][nt][half * 2] + b0v,
                                                       acc[mt][nt][half * 2 + 1] + b1v);
                }
            }
        }
    }
}

// ---------------------------------------------------------------------------
extern "C" void kernel_launch(void* const* d_in, const int* in_sizes, int n_in,
                              void* d_out, int out_size) {
    const float* x    = (const float*)d_in[0];
    const float* wqkv = (const float*)d_in[1];
    const float* pos  = (const float*)d_in[2];
    const float* wout = (const float*)d_in[3];
    const float* bout = (const float*)d_in[4];
    float* out = (float*)d_out;

    cudaFuncSetAttribute(qkv_tc, cudaFuncAttributeMaxDynamicSharedMemorySize, SMEM_BYTES);
    cudaFuncSetAttribute(out_tc, cudaFuncAttributeMaxDynamicSharedMemorySize, SMEM_BYTES);
    cudaFuncSetAttribute(attn_mma, cudaFuncAttributeMaxDynamicSharedMemorySize, ATTN_SMEM);

    bias_kernel<<<16, 256>>>(pos);
    wconv_kernel<<<(NQ * CDIM + 255) / 256, 256>>>(wqkv, wout);
    qkv_tc<<<MTOT / 64, 128, SMEM_BYTES>>>(x);
    attn_mma<<<BATCH * NWIN * 2, 384, ATTN_SMEM>>>();
    out_tc<<<MTOT / 64, 128, SMEM_BYTES>>>(bout, out);
}